// round 2
// baseline (speedup 1.0000x reference)
#include <cuda_runtime.h>
#include <math.h>

#define BB 4
#define SS 2048
#define DD 512
#define HH 8
#define DH 64   // DK == DV == 64

// ---------------- scratch (allocation-free: __device__ globals) ----------------
__device__ float g_q[BB * HH * SS * DH];    // (B,H,S,64)
__device__ float g_k[BB * HH * SS * DH];
__device__ float g_v[BB * HH * SS * DH];
__device__ float g_ctx[BB * SS * HH * DH];  // (B,S,512)

// ---------------- generic tiled SGEMM: C = A[M,K] @ W[K,N] + bias[N] ----------------
// BM=BN=64, BK=16, 256 threads, 4x4 micro-tile.
// SPLIT=true: write C into split-head layout (B,H,S,64) assuming N=512, S=2048, H=8.
template <bool SPLIT>
__global__ __launch_bounds__(256) void gemm_kernel(
    const float* __restrict__ A, const float* __restrict__ W,
    const float* __restrict__ bias, float* __restrict__ C,
    int M, int K, int N)
{
    __shared__ float As[16][64];  // k-major (transposed A tile)
    __shared__ float Ws[16][64];

    const int tid = threadIdx.x;
    const int tx = tid & 15;      // n group
    const int ty = tid >> 4;      // m group
    const int m0 = blockIdx.y * 64;
    const int n0 = blockIdx.x * 64;

    const int arow = tid >> 2, aseg = tid & 3;   // A tile load: 64 rows x 4 float4
    const int wrow = tid >> 4, wseg = tid & 15;  // W tile load: 16 rows x 16 float4

    float acc[4][4];
#pragma unroll
    for (int i = 0; i < 4; i++)
#pragma unroll
        for (int j = 0; j < 4; j++) acc[i][j] = 0.0f;

    for (int k0 = 0; k0 < K; k0 += 16) {
        float4 a4 = *reinterpret_cast<const float4*>(
            &A[(size_t)(m0 + arow) * K + k0 + aseg * 4]);
        As[aseg * 4 + 0][arow] = a4.x;
        As[aseg * 4 + 1][arow] = a4.y;
        As[aseg * 4 + 2][arow] = a4.z;
        As[aseg * 4 + 3][arow] = a4.w;
        float4 w4 = *reinterpret_cast<const float4*>(
            &W[(size_t)(k0 + wrow) * N + n0 + wseg * 4]);
        *reinterpret_cast<float4*>(&Ws[wrow][wseg * 4]) = w4;
        __syncthreads();

#pragma unroll
        for (int k = 0; k < 16; k++) {
            float4 av = *reinterpret_cast<const float4*>(&As[k][ty * 4]);
            float4 wv = *reinterpret_cast<const float4*>(&Ws[k][tx * 4]);
            float a[4] = {av.x, av.y, av.z, av.w};
            float w[4] = {wv.x, wv.y, wv.z, wv.w};
#pragma unroll
            for (int i = 0; i < 4; i++)
#pragma unroll
                for (int j = 0; j < 4; j++) acc[i][j] += a[i] * w[j];
        }
        __syncthreads();
    }

#pragma unroll
    for (int i = 0; i < 4; i++) {
        const int m = m0 + ty * 4 + i;
#pragma unroll
        for (int j = 0; j < 4; j++) {
            const int n = n0 + tx * 4 + j;
            const float v = acc[i][j] + bias[n];
            if (SPLIT) {
                const int b = m >> 11;      // / 2048
                const int s = m & 2047;
                const int h = n >> 6;
                const int d = n & 63;
                C[(((size_t)(b * HH + h)) * SS + s) * 64 + d] = v;
            } else {
                C[(size_t)m * N + n] = v;
            }
        }
    }
}

// ---------------- flash-attention kernel ----------------
// grid: (S/64, B*H), 256 threads. Tiles: 64 queries x 64 keys, dh=64.
// Reproduces the reference's fp32 mask-absorption semantics by adding the
// +-1e9 additive masks in fp32 (key-axis then query-axis, like the reference).
__global__ __launch_bounds__(256) void attn_kernel(
    const float* __restrict__ Q, const float* __restrict__ K,
    const float* __restrict__ V, const int* __restrict__ mask,
    float* __restrict__ ctx)
{
    extern __shared__ float sm[];
    float(*Qt)[68] = reinterpret_cast<float(*)[68]>(sm);             // Qt[d][r]
    float(*Kt)[68] = reinterpret_cast<float(*)[68]>(sm + 64 * 68);   // Kt[d][c]
    float(*Vs)[68] = reinterpret_cast<float(*)[68]>(sm + 2 * 64 * 68);  // Vs[k][d]
    float(*Ps)[68] = reinterpret_cast<float(*)[68]>(sm + 3 * 64 * 68);  // Ps[r][k]
    float* Mk = sm + 4 * 64 * 68;  // [64] key-mask additive values

    const int tid = threadIdx.x;
    const int tc = tid & 15;   // col group (keys in QK, dims in PV)
    const int tr = tid >> 4;   // row group (queries)
    const int bh = blockIdx.y;
    const int b = bh >> 3;     // H = 8
    const int h = bh & 7;
    const int q0 = blockIdx.x * 64;

    const float* Qb = Q + (size_t)bh * (SS * 64);
    const float* Kb = K + (size_t)bh * (SS * 64);
    const float* Vb = V + (size_t)bh * (SS * 64);
    const int* mrow = mask + b * SS;

    // load Q tile transposed (d-major)
    {
        const int row = tid >> 2, seg = tid & 3;
        const float4* src =
            reinterpret_cast<const float4*>(&Qb[(size_t)(q0 + row) * 64 + seg * 16]);
#pragma unroll
        for (int i = 0; i < 4; i++) {
            float4 v4 = src[i];
            const int d = seg * 16 + i * 4;
            Qt[d + 0][row] = v4.x;
            Qt[d + 1][row] = v4.y;
            Qt[d + 2][row] = v4.z;
            Qt[d + 3][row] = v4.w;
        }
    }

    float mq[4];
#pragma unroll
    for (int i = 0; i < 4; i++)
        mq[i] = mrow[q0 + tr * 4 + i] ? 0.0f : -1e9f;

    float m_i[4], l_i[4], acc[4][4];
#pragma unroll
    for (int i = 0; i < 4; i++) {
        m_i[i] = -3.0e38f;
        l_i[i] = 0.0f;
#pragma unroll
        for (int j = 0; j < 4; j++) acc[i][j] = 0.0f;
    }

    __syncthreads();

    for (int k0 = 0; k0 < SS; k0 += 64) {
        // load K tile (transposed, d-major) + V tile (k-major) + key mask
        {
            const int row = tid >> 2, seg = tid & 3;
            const float4* ksrc = reinterpret_cast<const float4*>(
                &Kb[(size_t)(k0 + row) * 64 + seg * 16]);
            const float4* vsrc = reinterpret_cast<const float4*>(
                &Vb[(size_t)(k0 + row) * 64 + seg * 16]);
#pragma unroll
            for (int i = 0; i < 4; i++) {
                const int d = seg * 16 + i * 4;
                float4 kv = ksrc[i];
                Kt[d + 0][row] = kv.x;
                Kt[d + 1][row] = kv.y;
                Kt[d + 2][row] = kv.z;
                Kt[d + 3][row] = kv.w;
                float4 vv = vsrc[i];
                *reinterpret_cast<float4*>(&Vs[row][d]) = vv;
            }
            if (tid < 64) Mk[tid] = mrow[k0 + tid] ? 0.0f : -1e9f;
        }
        __syncthreads();

        // scores: 4x4 micro-tile over Qt/Kt (both d-major)
        float s[4][4];
#pragma unroll
        for (int i = 0; i < 4; i++)
#pragma unroll
            for (int j = 0; j < 4; j++) s[i][j] = 0.0f;
#pragma unroll 8
        for (int d = 0; d < 64; d++) {
            float4 av = *reinterpret_cast<const float4*>(&Qt[d][tr * 4]);
            float4 bv = *reinterpret_cast<const float4*>(&Kt[d][tc * 4]);
            float a[4] = {av.x, av.y, av.z, av.w};
            float kk[4] = {bv.x, bv.y, bv.z, bv.w};
#pragma unroll
            for (int i = 0; i < 4; i++)
#pragma unroll
                for (int j = 0; j < 4; j++) s[i][j] += a[i] * kk[j];
        }
        float mkv[4];
#pragma unroll
        for (int j = 0; j < 4; j++) mkv[j] = Mk[tc * 4 + j];
#pragma unroll
        for (int i = 0; i < 4; i++)
#pragma unroll
            for (int j = 0; j < 4; j++)
                s[i][j] = (s[i][j] * 0.125f + mkv[j]) + mq[i];  // fp32 absorption as in ref

        // online softmax (row state replicated across the 16-lane col group)
        float p[4][4];
#pragma unroll
        for (int i = 0; i < 4; i++) {
            float tm = fmaxf(fmaxf(s[i][0], s[i][1]), fmaxf(s[i][2], s[i][3]));
#pragma unroll
            for (int off = 1; off < 16; off <<= 1)
                tm = fmaxf(tm, __shfl_xor_sync(0xffffffffu, tm, off));
            const float mn = fmaxf(m_i[i], tm);
            const float scale = __expf(m_i[i] - mn);
            float rs = 0.0f;
#pragma unroll
            for (int j = 0; j < 4; j++) {
                p[i][j] = __expf(s[i][j] - mn);
                rs += p[i][j];
            }
#pragma unroll
            for (int off = 1; off < 16; off <<= 1)
                rs += __shfl_xor_sync(0xffffffffu, rs, off);
            l_i[i] = l_i[i] * scale + rs;
            m_i[i] = mn;
#pragma unroll
            for (int j = 0; j < 4; j++) acc[i][j] *= scale;
        }
        // store P tile (r-major, float4, conflict-free)
#pragma unroll
        for (int i = 0; i < 4; i++) {
            float4 pv = make_float4(p[i][0], p[i][1], p[i][2], p[i][3]);
            *reinterpret_cast<float4*>(&Ps[tr * 4 + i][tc * 4]) = pv;
        }
        __syncthreads();

        // PV: acc[i][j] += sum_k Ps[r][k] * Vs[k][d]
#pragma unroll 4
        for (int k = 0; k < 64; k++) {
            float4 v4 = *reinterpret_cast<const float4*>(&Vs[k][tc * 4]);
            float vb[4] = {v4.x, v4.y, v4.z, v4.w};
            float pa[4];
#pragma unroll
            for (int i = 0; i < 4; i++) pa[i] = Ps[tr * 4 + i][k];
#pragma unroll
            for (int i = 0; i < 4; i++)
#pragma unroll
                for (int j = 0; j < 4; j++) acc[i][j] += pa[i] * vb[j];
        }
        __syncthreads();
    }

    // epilogue: normalize + write ctx in (B,S,H*64) layout
#pragma unroll
    for (int i = 0; i < 4; i++) {
        const float inv = 1.0f / l_i[i];
        const int q = q0 + tr * 4 + i;
        float4 o = make_float4(acc[i][0] * inv, acc[i][1] * inv,
                               acc[i][2] * inv, acc[i][3] * inv);
        *reinterpret_cast<float4*>(
            &ctx[((size_t)(b * SS + q)) * 512 + h * 64 + tc * 4]) = o;
    }
}

// ---------------- launch ----------------
extern "C" void kernel_launch(void* const* d_in, const int* in_sizes, int n_in,
                              void* d_out, int out_size)
{
    (void)in_sizes; (void)n_in; (void)out_size;
    const float* query = (const float*)d_in[0];
    const float* value = (const float*)d_in[1];
    const int*   amask = (const int*)d_in[2];
    const float* Wq = (const float*)d_in[3];
    const float* bq = (const float*)d_in[4];
    const float* Wk = (const float*)d_in[5];
    const float* bk = (const float*)d_in[6];
    const float* Wv = (const float*)d_in[7];
    const float* bv = (const float*)d_in[8];
    const float* Wo = (const float*)d_in[9];
    const float* bo = (const float*)d_in[10];
    float* out = (float*)d_out;

    float *pq, *pk, *pv, *pctx;
    cudaGetSymbolAddress((void**)&pq, g_q);
    cudaGetSymbolAddress((void**)&pk, g_k);
    cudaGetSymbolAddress((void**)&pv, g_v);
    cudaGetSymbolAddress((void**)&pctx, g_ctx);

    const int M = BB * SS;           // 8192
    const dim3 ggrid(DD / 64, M / 64);  // (8,128)

    // QKV projections into split-head layout
    gemm_kernel<true><<<ggrid, 256>>>(query, Wq, bq, pq, M, DD, HH * DH);
    gemm_kernel<true><<<ggrid, 256>>>(value, Wk, bk, pk, M, DD, HH * DH);
    gemm_kernel<true><<<ggrid, 256>>>(value, Wv, bv, pv, M, DD, HH * DH);

    // attention
    const int smem = (4 * 64 * 68 + 64) * sizeof(float);  // ~69.9 KB
    cudaFuncSetAttribute(attn_kernel, cudaFuncAttributeMaxDynamicSharedMemorySize, smem);
    attn_kernel<<<dim3(SS / 64, BB * HH), 256, smem>>>(pq, pk, pv, amask, pctx);

    // output projection
    gemm_kernel<false><<<ggrid, 256>>>(pctx, Wo, bo, out, M, HH * DH, DD);
}

// round 3
// speedup vs baseline: 1.7622x; 1.7622x over previous
#include <cuda_runtime.h>
#include <stdint.h>
#include <math.h>

#define BB 4
#define SS 2048
#define DD 512
#define HH 8

// ---------------- scratch (allocation-free: __device__ globals) ----------------
__device__ float g_q[BB * HH * SS * 64];    // (B,H,S,64)
__device__ float g_k[BB * HH * SS * 64];
__device__ float g_v[BB * HH * SS * 64];
__device__ float g_ctx[BB * SS * DD];       // (B,S,512)

// ---------------- helpers ----------------
__device__ __forceinline__ uint32_t f2tf(float x) {
    uint32_t r;
    asm("cvt.rna.tf32.f32 %0, %1;" : "=r"(r) : "f"(x));
    return r;
}

__device__ __forceinline__ void mma_tf32(float* c, const uint32_t* a, const uint32_t* b) {
    asm volatile(
        "mma.sync.aligned.m16n8k8.row.col.f32.tf32.tf32.f32 "
        "{%0,%1,%2,%3}, {%4,%5,%6,%7}, {%8,%9}, {%0,%1,%2,%3};\n"
        : "+f"(c[0]), "+f"(c[1]), "+f"(c[2]), "+f"(c[3])
        : "r"(a[0]), "r"(a[1]), "r"(a[2]), "r"(a[3]), "r"(b[0]), "r"(b[1]));
}

// FMA-pipe exp (avoids MUFU bottleneck). x <= 0 always here.
// Very negative x (masked -1e9 paths) -> ~2^-126 ~= 0, matching ref's exact-0
// underflow to within 1e-38 (negligible vs 1e-3 threshold).
__device__ __forceinline__ float fexp(float x) {
    float y = x * 1.4426950408889634f;     // log2(e)
    y = fmaxf(y, -126.0f);                 // also squashes -inf from overflowed args
    float n = rintf(y);
    float f = y - n;
    float p = 1.33335581e-3f;
    p = fmaf(p, f, 9.61812910e-3f);
    p = fmaf(p, f, 5.55041087e-2f);
    p = fmaf(p, f, 2.40226507e-1f);
    p = fmaf(p, f, 6.93147180e-1f);
    p = fmaf(p, f, 1.0f);
    int in = (int)n;
    float r = __int_as_float((in + 127) << 23);   // 2^n (n in [-126, 0])
    return p * r;
}

// ---------------- tensor-core SGEMM (tf32): C = A[M,K] @ W[K,N] + bias ----------------
// CTA tile 128x64, BK=16, 256 threads = 8 warps in 4(m) x 2(n); warp tile 32x32.
// SPLIT=true writes into split-head layout (B,H,S,64) assuming N=512, S=2048.
template <bool SPLIT>
__global__ __launch_bounds__(256) void gemm_tc(
    const float* __restrict__ A, const float* __restrict__ W,
    const float* __restrict__ bias, float* __restrict__ C,
    int M, int K, int N)
{
    __shared__ uint32_t As[16][132];  // [k][m], tf32 bits (132 mod 32 == 4 -> conflict-free frags)
    __shared__ uint32_t Ws[16][68];   // [k][n]

    const int tid = threadIdx.x;
    const int lane = tid & 31, warp = tid >> 5;
    const int gid = lane >> 2, t4 = lane & 3;
    const int wm = warp & 3, wn = warp >> 2;
    const int m0 = blockIdx.y * 128, n0 = blockIdx.x * 64;

    // gmem staging assignments
    const int ar = tid >> 1, ac = (tid & 1) * 8;   // A: row ar, k-cols ac..ac+7
    const int br = tid >> 4, bc = (tid & 15) * 4;  // W: row br, n-cols bc..bc+3

    const float* Aptr = A + (size_t)(m0 + ar) * K + ac;
    const float* Wptr = W + (size_t)br * N + n0 + bc;

    float acc[2][4][4];
#pragma unroll
    for (int i = 0; i < 2; i++)
#pragma unroll
        for (int j = 0; j < 4; j++)
#pragma unroll
            for (int k = 0; k < 4; k++) acc[i][j][k] = 0.0f;

    float4 apre0 = *reinterpret_cast<const float4*>(Aptr);
    float4 apre1 = *reinterpret_cast<const float4*>(Aptr + 4);
    float4 wpre  = *reinterpret_cast<const float4*>(Wptr);

    for (int k0 = 0; k0 < K; k0 += 16) {
        // stage (converted to tf32)
        As[ac + 0][ar] = f2tf(apre0.x);
        As[ac + 1][ar] = f2tf(apre0.y);
        As[ac + 2][ar] = f2tf(apre0.z);
        As[ac + 3][ar] = f2tf(apre0.w);
        As[ac + 4][ar] = f2tf(apre1.x);
        As[ac + 5][ar] = f2tf(apre1.y);
        As[ac + 6][ar] = f2tf(apre1.z);
        As[ac + 7][ar] = f2tf(apre1.w);
        Ws[br][bc + 0] = f2tf(wpre.x);
        Ws[br][bc + 1] = f2tf(wpre.y);
        Ws[br][bc + 2] = f2tf(wpre.z);
        Ws[br][bc + 3] = f2tf(wpre.w);
        __syncthreads();

        if (k0 + 16 < K) {  // prefetch next tile (overlaps with mma)
            apre0 = *reinterpret_cast<const float4*>(Aptr + k0 + 16);
            apre1 = *reinterpret_cast<const float4*>(Aptr + k0 + 20);
            wpre  = *reinterpret_cast<const float4*>(Wptr + (size_t)(k0 + 16) * N);
        }

#pragma unroll
        for (int ks = 0; ks < 2; ks++) {
            const int kk = ks * 8;
            uint32_t af[2][4], bf[4][2];
#pragma unroll
            for (int mf = 0; mf < 2; mf++) {
                const int mr = wm * 32 + mf * 16 + gid;
                af[mf][0] = As[kk + t4][mr];
                af[mf][1] = As[kk + t4][mr + 8];
                af[mf][2] = As[kk + t4 + 4][mr];
                af[mf][3] = As[kk + t4 + 4][mr + 8];
            }
#pragma unroll
            for (int nf = 0; nf < 4; nf++) {
                const int nc = wn * 32 + nf * 8 + gid;
                bf[nf][0] = Ws[kk + t4][nc];
                bf[nf][1] = Ws[kk + t4 + 4][nc];
            }
#pragma unroll
            for (int mf = 0; mf < 2; mf++)
#pragma unroll
                for (int nf = 0; nf < 4; nf++)
                    mma_tf32(acc[mf][nf], af[mf], bf[nf]);
        }
        __syncthreads();
    }

    // epilogue
#pragma unroll
    for (int mf = 0; mf < 2; mf++) {
#pragma unroll
        for (int half = 0; half < 2; half++) {
            const int m = m0 + wm * 32 + mf * 16 + gid + half * 8;
#pragma unroll
            for (int nf = 0; nf < 4; nf++) {
                const int n = n0 + wn * 32 + nf * 8 + t4 * 2;
                float2 v;
                v.x = acc[mf][nf][half * 2 + 0] + bias[n];
                v.y = acc[mf][nf][half * 2 + 1] + bias[n + 1];
                if (SPLIT) {
                    const int b = m >> 11, s = m & 2047;
                    const int h = n >> 6, d = n & 63;
                    *reinterpret_cast<float2*>(
                        &C[(((size_t)(b * HH + h)) * SS + s) * 64 + d]) = v;
                } else {
                    *reinterpret_cast<float2*>(&C[(size_t)m * N + n]) = v;
                }
            }
        }
    }
}

// ---------------- tensor-core flash attention ----------------
// CTA: 128 threads (4 warps), 64 queries. Each warp owns 16 query rows and the
// full 64-key tile, so flash row-state needs no cross-warp combine.
__global__ __launch_bounds__(128) void attn_tc(
    const float* __restrict__ Q, const float* __restrict__ K,
    const float* __restrict__ V, const int* __restrict__ mask,
    float* __restrict__ ctx)
{
    extern __shared__ uint32_t sm[];
    uint32_t(*Ks)[68] = reinterpret_cast<uint32_t(*)[68]>(sm);              // [key][d] tf32
    uint32_t(*Vs)[68] = reinterpret_cast<uint32_t(*)[68]>(sm + 64 * 68);    // [key][d] tf32
    uint32_t(*Ps)[68] = reinterpret_cast<uint32_t(*)[68]>(sm + 2 * 64 * 68);// [q][key] tf32
    float* Mk = reinterpret_cast<float*>(sm + 3 * 64 * 68);                 // [64]

    const int tid = threadIdx.x;
    const int lane = tid & 31, warp = tid >> 5;
    const int gid = lane >> 2, t4 = lane & 3;
    const int bh = blockIdx.y, b = bh >> 3, h = bh & 7;
    const int q0 = blockIdx.x * 64;

    const float* Qb = Q + (size_t)bh * SS * 64;
    const float* Kb = K + (size_t)bh * SS * 64;
    const float* Vb = V + (size_t)bh * SS * 64;
    const int* mrow = mask + b * SS;

    // Q a-fragments (loaded once, kept in regs)
    const int qr1 = q0 + warp * 16 + gid;
    const float* q1 = Qb + (size_t)qr1 * 64;
    const float* q2 = q1 + 8 * 64;
    uint32_t qa[8][4];
#pragma unroll
    for (int kf = 0; kf < 8; kf++) {
        qa[kf][0] = f2tf(q1[kf * 8 + t4]);
        qa[kf][1] = f2tf(q2[kf * 8 + t4]);
        qa[kf][2] = f2tf(q1[kf * 8 + t4 + 4]);
        qa[kf][3] = f2tf(q2[kf * 8 + t4 + 4]);
    }
    const float mq1 = mrow[qr1] ? 0.0f : -1e9f;
    const float mq2 = mrow[qr1 + 8] ? 0.0f : -1e9f;

    float m1 = -3e38f, m2 = -3e38f, l1 = 0.0f, l2 = 0.0f;
    float acc[8][4];
#pragma unroll
    for (int nf = 0; nf < 8; nf++)
#pragma unroll
        for (int j = 0; j < 4; j++) acc[nf][j] = 0.0f;

    const int fr = tid >> 1, fc = (tid & 1) * 32;  // K/V smem fill: 32 floats each

    for (int k0 = 0; k0 < SS; k0 += 64) {
        __syncthreads();  // prior tile's smem reads done
        {
            const float4* kp =
                reinterpret_cast<const float4*>(Kb + (size_t)(k0 + fr) * 64 + fc);
            const float4* vp =
                reinterpret_cast<const float4*>(Vb + (size_t)(k0 + fr) * 64 + fc);
#pragma unroll
            for (int i = 0; i < 8; i++) {
                float4 kv = kp[i];
                uint4 kt = make_uint4(f2tf(kv.x), f2tf(kv.y), f2tf(kv.z), f2tf(kv.w));
                *reinterpret_cast<uint4*>(&Ks[fr][fc + i * 4]) = kt;
                float4 vv = vp[i];
                uint4 vt = make_uint4(f2tf(vv.x), f2tf(vv.y), f2tf(vv.z), f2tf(vv.w));
                *reinterpret_cast<uint4*>(&Vs[fr][fc + i * 4]) = vt;
            }
            if (tid < 64) Mk[tid] = mrow[k0 + tid] ? 0.0f : -1e9f;
        }
        __syncthreads();

        // ---- QK^T: 16x64 scores per warp ----
        float sf[8][4];
#pragma unroll
        for (int nf = 0; nf < 8; nf++)
#pragma unroll
            for (int j = 0; j < 4; j++) sf[nf][j] = 0.0f;
#pragma unroll
        for (int kf = 0; kf < 8; kf++) {
#pragma unroll
            for (int nf = 0; nf < 8; nf++) {
                uint32_t bf[2];
                bf[0] = Ks[nf * 8 + gid][kf * 8 + t4];
                bf[1] = Ks[nf * 8 + gid][kf * 8 + t4 + 4];
                mma_tf32(sf[nf], qa[kf], bf);
            }
        }

        // ---- masked online softmax ----
        float tm1 = -3e38f, tm2 = -3e38f;
#pragma unroll
        for (int nf = 0; nf < 8; nf++) {
            const float mk0 = Mk[nf * 8 + t4 * 2];
            const float mk1 = Mk[nf * 8 + t4 * 2 + 1];
            float v0 = (sf[nf][0] * 0.125f + mk0) + mq1;  // fp32 absorption as in ref
            float v1 = (sf[nf][1] * 0.125f + mk1) + mq1;
            float v2 = (sf[nf][2] * 0.125f + mk0) + mq2;
            float v3 = (sf[nf][3] * 0.125f + mk1) + mq2;
            sf[nf][0] = v0; sf[nf][1] = v1; sf[nf][2] = v2; sf[nf][3] = v3;
            tm1 = fmaxf(tm1, fmaxf(v0, v1));
            tm2 = fmaxf(tm2, fmaxf(v2, v3));
        }
        tm1 = fmaxf(tm1, __shfl_xor_sync(0xffffffffu, tm1, 1));
        tm1 = fmaxf(tm1, __shfl_xor_sync(0xffffffffu, tm1, 2));
        tm2 = fmaxf(tm2, __shfl_xor_sync(0xffffffffu, tm2, 1));
        tm2 = fmaxf(tm2, __shfl_xor_sync(0xffffffffu, tm2, 2));

        const float mn1 = fmaxf(m1, tm1), mn2 = fmaxf(m2, tm2);
        const float sc1 = fexp(m1 - mn1), sc2 = fexp(m2 - mn2);
        float rs1 = 0.0f, rs2 = 0.0f;
        const int pr = warp * 16 + gid;
#pragma unroll
        for (int nf = 0; nf < 8; nf++) {
            float p0 = fexp(sf[nf][0] - mn1);
            float p1 = fexp(sf[nf][1] - mn1);
            rs1 += p0 + p1;
            *reinterpret_cast<uint2*>(&Ps[pr][nf * 8 + t4 * 2]) =
                make_uint2(f2tf(p0), f2tf(p1));
            float p2 = fexp(sf[nf][2] - mn2);
            float p3 = fexp(sf[nf][3] - mn2);
            rs2 += p2 + p3;
            *reinterpret_cast<uint2*>(&Ps[pr + 8][nf * 8 + t4 * 2]) =
                make_uint2(f2tf(p2), f2tf(p3));
        }
        rs1 += __shfl_xor_sync(0xffffffffu, rs1, 1);
        rs1 += __shfl_xor_sync(0xffffffffu, rs1, 2);
        rs2 += __shfl_xor_sync(0xffffffffu, rs2, 1);
        rs2 += __shfl_xor_sync(0xffffffffu, rs2, 2);

        l1 = l1 * sc1 + rs1; m1 = mn1;
        l2 = l2 * sc2 + rs2; m2 = mn2;
#pragma unroll
        for (int nf = 0; nf < 8; nf++) {
            acc[nf][0] *= sc1; acc[nf][1] *= sc1;
            acc[nf][2] *= sc2; acc[nf][3] *= sc2;
        }
        __syncwarp();  // Ps is warp-private: order STS before LDS within warp

        // ---- P @ V ----
#pragma unroll
        for (int kf = 0; kf < 8; kf++) {
            uint32_t pa[4];
            pa[0] = Ps[warp * 16 + gid][kf * 8 + t4];
            pa[1] = Ps[warp * 16 + gid + 8][kf * 8 + t4];
            pa[2] = Ps[warp * 16 + gid][kf * 8 + t4 + 4];
            pa[3] = Ps[warp * 16 + gid + 8][kf * 8 + t4 + 4];
#pragma unroll
            for (int nf = 0; nf < 8; nf++) {
                uint32_t vb[2];
                vb[0] = Vs[kf * 8 + t4][nf * 8 + gid];
                vb[1] = Vs[kf * 8 + t4 + 4][nf * 8 + gid];
                mma_tf32(acc[nf], pa, vb);
            }
        }
    }

    // epilogue: normalize, write ctx in (B,S,H*64)
    const float i1 = 1.0f / l1, i2 = 1.0f / l2;
    float* o1 = ctx + ((size_t)(b * SS + qr1)) * DD + h * 64;
    float* o2 = o1 + 8 * DD;
#pragma unroll
    for (int nf = 0; nf < 8; nf++) {
        *reinterpret_cast<float2*>(&o1[nf * 8 + t4 * 2]) =
            make_float2(acc[nf][0] * i1, acc[nf][1] * i1);
        *reinterpret_cast<float2*>(&o2[nf * 8 + t4 * 2]) =
            make_float2(acc[nf][2] * i2, acc[nf][3] * i2);
    }
}

// ---------------- launch ----------------
extern "C" void kernel_launch(void* const* d_in, const int* in_sizes, int n_in,
                              void* d_out, int out_size)
{
    (void)in_sizes; (void)n_in; (void)out_size;
    const float* query = (const float*)d_in[0];
    const float* value = (const float*)d_in[1];
    const int*   amask = (const int*)d_in[2];
    const float* Wq = (const float*)d_in[3];
    const float* bq = (const float*)d_in[4];
    const float* Wk = (const float*)d_in[5];
    const float* bk = (const float*)d_in[6];
    const float* Wv = (const float*)d_in[7];
    const float* bv = (const float*)d_in[8];
    const float* Wo = (const float*)d_in[9];
    const float* bo = (const float*)d_in[10];
    float* out = (float*)d_out;

    float *pq, *pk, *pv, *pctx;
    cudaGetSymbolAddress((void**)&pq, g_q);
    cudaGetSymbolAddress((void**)&pk, g_k);
    cudaGetSymbolAddress((void**)&pv, g_v);
    cudaGetSymbolAddress((void**)&pctx, g_ctx);

    const int M = BB * SS;              // 8192
    const dim3 ggrid(DD / 64, M / 128); // (8, 64)

    gemm_tc<true><<<ggrid, 256>>>(query, Wq, bq, pq, M, DD, DD);
    gemm_tc<true><<<ggrid, 256>>>(value, Wk, bk, pk, M, DD, DD);
    gemm_tc<true><<<ggrid, 256>>>(value, Wv, bv, pv, M, DD, DD);

    const int smem = (3 * 64 * 68) * 4 + 64 * 4;  // ~52.5 KB
    cudaFuncSetAttribute(attn_tc, cudaFuncAttributeMaxDynamicSharedMemorySize, smem);
    attn_tc<<<dim3(SS / 64, BB * HH), 128, smem>>>(pq, pk, pv, amask, pctx);

    gemm_tc<false><<<ggrid, 256>>>(pctx, Wo, bo, out, M, DD, DD);
}